// round 14
// baseline (speedup 1.0000x reference)
#include <cuda_runtime.h>
#include <cuda_bf16.h>
#include <cstdint>

#define BB 2048
#define TT 512
#define VOCAB 4
#define EE 64
#define HH 128
#define G3 384
#define NBLK 148
#define MROWS 14
#define BPAD (NBLK * MROWS)
#define NTHR 512
#define GISTR 388      // gi row stride (padded to break bank alignment)

// ---- scratch (no allocs allowed) ----
__device__ float         g_gi[VOCAB * G3];   // b_ih (+ b_hh for r,z) folded in
__device__ unsigned char g_tok[TT * BPAD];   // zero-init => pad rows v=0
__device__ int           g_is64;

// ---- smem layout (bytes) ----
#define OFF_BF   0          // B frags (W hi+lo), 48 tiles*16kt*256B = 196608
#define OFF_AH0  196608     // h-hi buf 0: 16*64 u32 = 4096
#define OFF_AL0  200704     // h-lo buf 0
#define OFF_AH1  204800     // h-hi buf 1
#define OFF_AL1  208896     // h-lo buf 1
#define OFF_GI   212992     // 4*GISTR f32 = 6208
#define OFF_TOK  219200     // 2*16 int = 128
#define SMEM_BYTES 219328

__device__ __forceinline__ float tanh_fast(float x) {
    float y;
    asm("tanh.approx.f32 %0, %1;" : "=f"(y) : "f"(x));
    return y;
}
__device__ __forceinline__ float sigmoid_fast(float x) {
    return fmaf(tanh_fast(0.5f * x), 0.5f, 0.5f);
}
__device__ __forceinline__ uint32_t pk2(float a, float b) {   // lo=a, hi=b, rn
    uint32_t r;
    asm("cvt.rn.bf16x2.f32 %0, %1, %2;" : "=r"(r) : "f"(b), "f"(a));
    return r;
}
__device__ __forceinline__ float unpk_lo(uint32_t p) {
    return __bfloat162float(__ushort_as_bfloat16((unsigned short)(p & 0xffffu)));
}
__device__ __forceinline__ float unpk_hi(uint32_t p) {
    return __bfloat162float(__ushort_as_bfloat16((unsigned short)(p >> 16)));
}
__device__ __forceinline__ float bf_res(float x) {
    return x - __bfloat162float(__float2bfloat16(x));
}
__device__ __forceinline__ void mma_bf16(float c[4], const uint32_t a[4],
                                         uint64_t b) {
    uint32_t b0 = (uint32_t)b, b1 = (uint32_t)(b >> 32);
    asm("mma.sync.aligned.m16n8k16.row.col.f32.bf16.bf16.f32 "
        "{%0,%1,%2,%3}, {%4,%5,%6,%7}, {%8,%9}, {%0,%1,%2,%3};"
        : "+f"(c[0]), "+f"(c[1]), "+f"(c[2]), "+f"(c[3])
        : "r"(a[0]), "r"(a[1]), "r"(a[2]), "r"(a[3]), "r"(b0), "r"(b1));
}

__global__ void detect_kernel(const int* __restrict__ x32) {
    int all_zero = 1;
    for (int i = 1; i < 128; i += 2) all_zero &= (x32[i] == 0);
    g_is64 = all_zero;
}

__global__ void tok_kernel(const void* __restrict__ xraw) {
    int i = blockIdx.x * blockDim.x + threadIdx.x;
    if (i >= BB * TT) return;
    int b = i / TT, t = i % TT;
    int v;
    if (g_is64) v = (int)((const long long*)xraw)[i];
    else        v = ((const int*)xraw)[i];
    g_tok[t * BPAD + b] = (unsigned char)v;
}

// gi[v][g] = b_ih[g] + W_ih[g]·emb[v]  (+ b_hh[g] for gates r,z: g<256)
__global__ void gi_kernel(const float* __restrict__ W_ih,
                          const float* __restrict__ emb,
                          const float* __restrict__ b_ih,
                          const float* __restrict__ b_hh) {
    int g = threadIdx.x;
    if (g >= G3) return;
    float bi = b_ih[g] + (g < 256 ? b_hh[g] : 0.0f);
    for (int v = 0; v < VOCAB; ++v) {
        float s = bi;
#pragma unroll 8
        for (int e = 0; e < EE; ++e) s += W_ih[g * EE + e] * emb[v * EE + e];
        g_gi[v * G3 + g] = s;
    }
}

extern __shared__ char smem[];

__global__ __launch_bounds__(NTHR, 1)
void gru_kernel(const float* __restrict__ W_hh, const float* __restrict__ b_hh,
                const float* __restrict__ W_fc, const float* __restrict__ b_fc,
                float* __restrict__ out) {
    uint64_t* BF     = (uint64_t*)(smem + OFF_BF);
    uint32_t* AHb[2] = {(uint32_t*)(smem + OFF_AH0), (uint32_t*)(smem + OFF_AH1)};
    uint32_t* ALb[2] = {(uint32_t*)(smem + OFF_AL0), (uint32_t*)(smem + OFF_AL1)};
    float*    gi_s   = (float*)(smem + OFF_GI);
    int*      tok_s  = (int*)(smem + OFF_TOK);

    const int tid = threadIdx.x;       // 0..511
    const int l   = tid & 31;
    const int w   = tid >> 5;          // warp 0..15: units [8w, 8w+8)
    const int lg  = l >> 2;            // mma group (row)
    const int lt  = l & 3;             // mma thread-in-group
    const int swl = lg << 2;           // A swizzle
    const int row0 = blockIdx.x * MROWS;

    // ---- stage W hi/lo fragments into smem (frag-ordered, one-time) ----
    // tile instance tw = w*3 + g  (g = gate 0..2); entry = l + 32*(kt + 16*tw)
    for (int idx = tid; idx < 24576; idx += NTHR) {
        int ll = idx & 31, kt = (idx >> 5) & 15, tw = idx >> 9;
        int g = tw % 3, ww = tw / 3;
        int n = g * 128 + 8 * ww + (ll >> 2);
        int k = (kt & 7) * 16 + (ll & 3) * 2;
        const float* Wn = W_hh + n * HH + k;
        float x0 = Wn[0], x1 = Wn[1], x2 = Wn[8], x3 = Wn[9];
        uint32_t b0, b1;
        if (kt < 8) { b0 = pk2(x0, x1); b1 = pk2(x2, x3); }
        else { b0 = pk2(bf_res(x0), bf_res(x1));
               b1 = pk2(bf_res(x2), bf_res(x3)); }
        BF[idx] = (uint64_t)b0 | ((uint64_t)b1 << 32);
    }
    for (int i = tid; i < 1024; i += NTHR) {
        AHb[0][i] = 0; ALb[0][i] = 0; AHb[1][i] = 0; ALb[1][i] = 0;
    }
    for (int i = tid; i < VOCAB * G3; i += NTHR)
        gi_s[(i / G3) * GISTR + (i % G3)] = g_gi[i];
    if (tid < 16) {
        tok_s[tid]      = (tid < MROWS) ? (g_tok[row0 + tid] & 3) : 0;
        tok_s[16 + tid] = 0;
    }
    // n-gate bias for this thread's 2 units (r,z folded into gi table)
    float bN0 = b_hh[256 + 8 * w + 2 * lt];
    float bN1 = b_hh[256 + 8 * w + 2 * lt + 1];
    __syncthreads();

    // ---- hoist W-hi fragments into registers (3 tiles x 8 kt = 48 regs) ----
    uint64_t Whi[24];
#pragma unroll
    for (int g = 0; g < 3; ++g)
#pragma unroll
        for (int kt = 0; kt < 8; ++kt)
            Whi[g * 8 + kt] = BF[(w * 3 + g) * 512 + kt * 32 + l];
    // W-lo stays in smem
    const uint64_t* BloB = BF + (w * 3) * 512 + 256 + l;   // [g*512 + kt*32]

    float hreg[2][2];   // [row-half rh][col c]
    hreg[0][0] = hreg[0][1] = hreg[1][0] = hreg[1][1] = 0.f;

    for (int t = 0; t < TT; ++t) {
        const int cur = t & 1, nxt = cur ^ 1;
        const uint32_t* Ah = AHb[cur];
        const uint32_t* Al = ALb[cur];

        int ntv = 0;
        if (tid < MROWS && t + 1 < TT)
            ntv = g_tok[(t + 1) * BPAD + row0 + tid] & 3;

        // ---- load A-hi fragments (resident across passes 1 and 3) ----
        uint32_t Afh[8][4];
#pragma unroll
        for (int kc = 0; kc < 8; ++kc) {
            int w0 = kc * 8 + lt;
            int p0 = lg * 64 + (w0 ^ swl);
            int p2 = lg * 64 + ((w0 + 4) ^ swl);
            Afh[kc][0] = Ah[p0];       Afh[kc][1] = Ah[p0 + 512];
            Afh[kc][2] = Ah[p2];       Afh[kc][3] = Ah[p2 + 512];
        }

        float C[3][4];
        C[0][0] = C[0][1] = C[0][2] = C[0][3] = 0.f;   // r
        C[1][0] = C[1][1] = C[1][2] = C[1][3] = 0.f;   // z
        C[2][0] = bN0; C[2][1] = bN1; C[2][2] = bN0; C[2][3] = bN1;  // n

        // ---- pass 1: A-hi x W-hi (all registers) ----
#pragma unroll
        for (int kt = 0; kt < 8; ++kt)
#pragma unroll
            for (int g = 0; g < 3; ++g)
                mma_bf16(C[g], Afh[kt], Whi[g * 8 + kt]);

        // ---- pass 2: A-lo x W-hi (A streamed per kt, B in registers) ----
#pragma unroll
        for (int kt = 0; kt < 8; ++kt) {
            uint32_t a[4];
            int w0 = kt * 8 + lt;
            int p0 = lg * 64 + (w0 ^ swl);
            int p2 = lg * 64 + ((w0 + 4) ^ swl);
            a[0] = Al[p0];       a[1] = Al[p0 + 512];
            a[2] = Al[p2];       a[3] = Al[p2 + 512];
#pragma unroll
            for (int g = 0; g < 3; ++g)
                mma_bf16(C[g], a, Whi[g * 8 + kt]);
        }

        // ---- pass 3: A-hi x W-lo (B from smem) ----
#pragma unroll
        for (int kt = 0; kt < 8; ++kt)
#pragma unroll
            for (int g = 0; g < 3; ++g)
                mma_bf16(C[g], Afh[kt], BloB[g * 512 + kt * 32]);

        // ---- gates + h update (4 cells, thread-local) ----
        uint32_t* AhN = AHb[nxt];
        uint32_t* AlN = ALb[nxt];
#pragma unroll
        for (int rh = 0; rh < 2; ++rh) {
            int m = lg + 8 * rh;
            int v = tok_s[cur * 16 + m];
            const float* gv = gi_s + v * GISTR + 8 * w + 2 * lt;
            float hn01[2];
#pragma unroll
            for (int c = 0; c < 2; ++c) {
                int  reg = 2 * rh + c;
                float r = sigmoid_fast(gv[c]       + C[0][reg]);
                float z = sigmoid_fast(gv[128 + c] + C[1][reg]);
                float n = tanh_fast   (gv[256 + c] + r * C[2][reg]);
                float hn = fmaf(z, hreg[rh][c] - n, n);
                hreg[rh][c] = hn;
                hn01[c] = hn;
            }
            uint32_t phi = pk2(hn01[0], hn01[1]);
            uint32_t plo = pk2(hn01[0] - unpk_lo(phi), hn01[1] - unpk_hi(phi));
            int word = (4 * w + lt) ^ swl;   // conflict-free vs lanes
            AhN[m * 64 + word] = phi;
            AlN[m * 64 + word] = plo;
        }
        if (tid < MROWS) tok_s[nxt * 16 + tid] = ntv;
        __syncthreads();
    }

    // ---- final h (fp32, from regs) -> smem (reuse BF region) ----
    float* hf = (float*)(smem + OFF_BF);
#pragma unroll
    for (int rh = 0; rh < 2; ++rh)
#pragma unroll
        for (int c = 0; c < 2; ++c) {
            int m = lg + 8 * rh;
            int u = 8 * w + 2 * lt + c;
            hf[m * HH + u] = hreg[rh][c];
        }
    __syncthreads();

    // ---- logits = hT @ W_fc.T + b_fc ----
    if (tid < MROWS * VOCAB) {
        int m = tid >> 2, v = tid & 3;
        int row = row0 + m;
        if (row < BB) {
            float        sum = b_fc[v];
            const float* wv  = W_fc + v * HH;
            const float* hr  = hf + m * HH;
#pragma unroll 8
            for (int k = 0; k < HH; ++k) sum = fmaf(hr[k], wv[k], sum);
            out[row * VOCAB + v] = sum;
        }
    }
}

extern "C" void kernel_launch(void* const* d_in, const int* in_sizes, int n_in,
                              void* d_out, int out_size) {
    const void*  x    = d_in[0];
    const float* emb  = (const float*)d_in[1];
    const float* W_ih = (const float*)d_in[2];
    const float* W_hh = (const float*)d_in[3];
    const float* b_ih = (const float*)d_in[4];
    const float* b_hh = (const float*)d_in[5];
    const float* W_fc = (const float*)d_in[6];
    const float* b_fc = (const float*)d_in[7];
    float* out = (float*)d_out;

    static int smem_set = 0;
    if (!smem_set) {
        cudaFuncSetAttribute(gru_kernel,
                             cudaFuncAttributeMaxDynamicSharedMemorySize,
                             SMEM_BYTES);
        smem_set = 1;
    }

    detect_kernel<<<1, 1>>>((const int*)x);
    tok_kernel<<<(BB * TT + 255) / 256, 256>>>(x);
    gi_kernel<<<1, G3>>>(W_ih, emb, b_ih, b_hh);
    gru_kernel<<<NBLK, NTHR, SMEM_BYTES>>>(W_hh, b_hh, W_fc, b_fc, out);
}

// round 15
// speedup vs baseline: 1.6598x; 1.6598x over previous
#include <cuda_runtime.h>
#include <cuda_fp16.h>
#include <cstdint>

#define BB 2048
#define TT 512
#define VOCAB 4
#define EE 64
#define HH 128
#define G3 384
#define NBLK 148
#define MROWS 14
#define BPAD (NBLK * MROWS)
#define NTHR 256
#define GISTR 388      // gi row stride (padded to break bank alignment)

// ---- scratch (no allocs allowed) ----
__device__ float         g_gi[VOCAB * G3];   // b_ih (+ b_hh for r,z) folded in
__device__ unsigned char g_tok[TT * BPAD];   // zero-init => pad rows v=0
__device__ int           g_is64;

// ---- smem layout (bytes) ----
#define OFF_BF   0          // W frags fp16: 48 tiles*8kt*256B = 98304
#define OFF_AH0  98304      // h-hi buf 0: 16*64 u32 = 4096
#define OFF_AL0  102400     // h-lo buf 0
#define OFF_AH1  106496     // h-hi buf 1
#define OFF_AL1  110592     // h-lo buf 1
#define OFF_GI   114688     // 4*GISTR f32 = 6208
#define OFF_TOK  120896     // 2*16 int = 128
#define SMEM_BYTES 121024

__device__ __forceinline__ float tanh_fast(float x) {
    float y;
    asm("tanh.approx.f32 %0, %1;" : "=f"(y) : "f"(x));
    return y;
}
__device__ __forceinline__ float sigmoid_fast(float x) {
    return fmaf(tanh_fast(0.5f * x), 0.5f, 0.5f);
}
// pack two f32 -> f16x2 (lo half = a, hi half = b), rn
__device__ __forceinline__ uint32_t pk2(float a, float b) {
    uint32_t r;
    asm("cvt.rn.f16x2.f32 %0, %1, %2;" : "=r"(r) : "f"(b), "f"(a));
    return r;
}
__device__ __forceinline__ float unpk_lo(uint32_t p) {
    return __half2float(__ushort_as_half((unsigned short)(p & 0xffffu)));
}
__device__ __forceinline__ float unpk_hi(uint32_t p) {
    return __half2float(__ushort_as_half((unsigned short)(p >> 16)));
}
__device__ __forceinline__ void mma_f16(float c[4], const uint32_t a[4],
                                        uint64_t b) {
    uint32_t b0 = (uint32_t)b, b1 = (uint32_t)(b >> 32);
    asm("mma.sync.aligned.m16n8k16.row.col.f32.f16.f16.f32 "
        "{%0,%1,%2,%3}, {%4,%5,%6,%7}, {%8,%9}, {%0,%1,%2,%3};"
        : "+f"(c[0]), "+f"(c[1]), "+f"(c[2]), "+f"(c[3])
        : "r"(a[0]), "r"(a[1]), "r"(a[2]), "r"(a[3]), "r"(b0), "r"(b1));
}

__global__ void detect_kernel(const int* __restrict__ x32) {
    int all_zero = 1;
    for (int i = 1; i < 128; i += 2) all_zero &= (x32[i] == 0);
    g_is64 = all_zero;
}

__global__ void tok_kernel(const void* __restrict__ xraw) {
    int i = blockIdx.x * blockDim.x + threadIdx.x;
    if (i >= BB * TT) return;
    int b = i / TT, t = i % TT;
    int v;
    if (g_is64) v = (int)((const long long*)xraw)[i];
    else        v = ((const int*)xraw)[i];
    g_tok[t * BPAD + b] = (unsigned char)v;
}

// gi[v][g] = b_ih[g] + W_ih[g]·emb[v]  (+ b_hh[g] for gates r,z: g<256)
__global__ void gi_kernel(const float* __restrict__ W_ih,
                          const float* __restrict__ emb,
                          const float* __restrict__ b_ih,
                          const float* __restrict__ b_hh) {
    int g = threadIdx.x;
    if (g >= G3) return;
    float bi = b_ih[g] + (g < 256 ? b_hh[g] : 0.0f);
    for (int v = 0; v < VOCAB; ++v) {
        float s = bi;
#pragma unroll 8
        for (int e = 0; e < EE; ++e) s += W_ih[g * EE + e] * emb[v * EE + e];
        g_gi[v * G3 + g] = s;
    }
}

extern __shared__ char smem[];

__global__ __launch_bounds__(NTHR, 1)
void gru_kernel(const float* __restrict__ W_hh, const float* __restrict__ b_hh,
                const float* __restrict__ W_fc, const float* __restrict__ b_fc,
                float* __restrict__ out) {
    uint64_t* BF     = (uint64_t*)(smem + OFF_BF);
    uint32_t* AHb[2] = {(uint32_t*)(smem + OFF_AH0), (uint32_t*)(smem + OFF_AH1)};
    uint32_t* ALb[2] = {(uint32_t*)(smem + OFF_AL0), (uint32_t*)(smem + OFF_AL1)};
    float*    gi_s   = (float*)(smem + OFF_GI);
    int*      tok_s  = (int*)(smem + OFF_TOK);

    const int tid = threadIdx.x;       // 0..255
    const int l   = tid & 31;
    const int w   = tid >> 5;          // warp 0..7: units [16w, 16w+16)
    const int lg  = l >> 2;            // mma group (row)
    const int lt  = l & 3;             // mma thread-in-group (col pair)
    const int swl = lg << 2;           // A swizzle for rows lg / lg+8
    const int row0 = blockIdx.x * MROWS;

    // ---- stage W fp16 fragments into smem (frag-ordered, one-time) ----
    // entry idx = l + 32*(kt + 8*(tile + 6*warp)),  48 tiles x 8 kt
    for (int idx = tid; idx < 12288; idx += NTHR) {
        int ll = idx & 31, kt = (idx >> 5) & 7, tw = idx >> 8;
        int tile = tw % 6, ww = tw / 6;
        int n = (tile >> 1) * 128 + 16 * ww + 8 * (tile & 1) + (ll >> 2);
        int k = kt * 16 + (ll & 3) * 2;
        const float* Wn = W_hh + n * HH + k;
        uint32_t b0 = pk2(Wn[0], Wn[1]);
        uint32_t b1 = pk2(Wn[8], Wn[9]);
        BF[idx] = (uint64_t)b0 | ((uint64_t)b1 << 32);
    }
    for (int i = tid; i < 1024; i += NTHR) {
        AHb[0][i] = 0; ALb[0][i] = 0; AHb[1][i] = 0; ALb[1][i] = 0;
    }
    for (int i = tid; i < VOCAB * G3; i += NTHR)
        gi_s[(i / G3) * GISTR + (i % G3)] = g_gi[i];
    if (tid < 16) {
        tok_s[tid]      = (tid < MROWS) ? (g_tok[row0 + tid] & 3) : 0;
        tok_s[16 + tid] = 0;
    }
    // n-gate bias only (r,z folded into gi table)
    float bN[2][2];
#pragma unroll
    for (int hp = 0; hp < 2; ++hp)
#pragma unroll
        for (int c = 0; c < 2; ++c)
            bN[hp][c] = b_hh[256 + 16 * w + 8 * hp + 2 * lt + c];
    __syncthreads();

    // ---- hoist ALL W fragments into registers (loop-invariant, fp16) ----
    uint64_t Wf[48];                        // [ti*8 + kt]
#pragma unroll
    for (int ti = 0; ti < 6; ++ti)
#pragma unroll
        for (int kt = 0; kt < 8; ++kt)
            Wf[ti * 8 + kt] = BF[(w * 6 + ti) * 256 + kt * 32 + l];

    float hreg[2][2][2];   // [h-half hp][row-half rh][col c]
#pragma unroll
    for (int hp = 0; hp < 2; ++hp)
#pragma unroll
        for (int rh = 0; rh < 2; ++rh) { hreg[hp][rh][0] = 0.f; hreg[hp][rh][1] = 0.f; }

    for (int t = 0; t < TT; ++t) {
        const int cur = t & 1, nxt = cur ^ 1;
        const uint32_t* Ah = AHb[cur];
        const uint32_t* Al = ALb[cur];

        int ntv = 0;
        if (tid < MROWS && t + 1 < TT)
            ntv = g_tok[(t + 1) * BPAD + row0 + tid] & 3;

        // ---- load ALL A fragments upfront (deep MLP batch) ----
        uint32_t Afh[8][4], Afl[8][4];
#pragma unroll
        for (int kc = 0; kc < 8; ++kc) {
            int w0 = kc * 8 + lt;
            int p0 = lg * 64 + (w0 ^ swl);
            int p2 = lg * 64 + ((w0 + 4) ^ swl);
            Afh[kc][0] = Ah[p0];       Afh[kc][1] = Ah[p0 + 512];
            Afh[kc][2] = Ah[p2];       Afh[kc][3] = Ah[p2 + 512];
            Afl[kc][0] = Al[p0];       Afl[kc][1] = Al[p0 + 512];
            Afl[kc][2] = Al[p2];       Afl[kc][3] = Al[p2 + 512];
        }

        float C[6][4];
#pragma unroll
        for (int ti = 0; ti < 4; ++ti) {       // r,z gates: bias in gi table
            C[ti][0] = 0.f; C[ti][1] = 0.f; C[ti][2] = 0.f; C[ti][3] = 0.f;
        }
#pragma unroll
        for (int hp = 0; hp < 2; ++hp) {       // n gate: bias inside r*( )
            C[4 + hp][0] = bN[hp][0]; C[4 + hp][1] = bN[hp][1];
            C[4 + hp][2] = bN[hp][0]; C[4 + hp][3] = bN[hp][1];
        }

        // ---- pass 1: A-hi x W (all registers) ----
#pragma unroll
        for (int kt = 0; kt < 8; ++kt)
#pragma unroll
            for (int ti = 0; ti < 6; ++ti)
                mma_f16(C[ti], Afh[kt], Wf[ti * 8 + kt]);

        // ---- pass 2: A-lo x W (all registers) ----
#pragma unroll
        for (int kt = 0; kt < 8; ++kt)
#pragma unroll
            for (int ti = 0; ti < 6; ++ti)
                mma_f16(C[ti], Afl[kt], Wf[ti * 8 + kt]);

        // ---- gates + h update (thread-local via C-frag ownership) ----
        uint32_t* AhN = AHb[nxt];
        uint32_t* AlN = ALb[nxt];
#pragma unroll
        for (int hp = 0; hp < 2; ++hp) {
#pragma unroll
            for (int rh = 0; rh < 2; ++rh) {
                int m = lg + 8 * rh;
                int v = tok_s[cur * 16 + m];
                const float* gv = gi_s + v * GISTR + 16 * w + 8 * hp + 2 * lt;
                float hn01[2];
#pragma unroll
                for (int c = 0; c < 2; ++c) {
                    int  reg = 2 * rh + c;
                    float r = sigmoid_fast(gv[c]       + C[hp][reg]);
                    float z = sigmoid_fast(gv[128 + c] + C[2 + hp][reg]);
                    float n = tanh_fast   (gv[256 + c] + r * C[4 + hp][reg]);
                    float hn = fmaf(z, hreg[hp][rh][c] - n, n);
                    hreg[hp][rh][c] = hn;
                    hn01[c] = hn;
                }
                uint32_t phi = pk2(hn01[0], hn01[1]);
                uint32_t plo = pk2(hn01[0] - unpk_lo(phi),
                                   hn01[1] - unpk_hi(phi));
                int word = (8 * w + 4 * hp + lt) ^ swl;   // swizzle f(m&7)=lg
                AhN[m * 64 + word] = phi;
                AlN[m * 64 + word] = plo;
            }
        }
        if (tid < MROWS) tok_s[nxt * 16 + tid] = ntv;
        __syncthreads();
    }

    // ---- final h (fp32, from regs) -> smem (reuse BF region) ----
    float* hf = (float*)(smem + OFF_BF);
#pragma unroll
    for (int hp = 0; hp < 2; ++hp)
#pragma unroll
        for (int rh = 0; rh < 2; ++rh)
#pragma unroll
            for (int c = 0; c < 2; ++c) {
                int m = lg + 8 * rh;
                int u = 16 * w + 8 * hp + 2 * lt + c;
                hf[m * HH + u] = hreg[hp][rh][c];
            }
    __syncthreads();

    // ---- logits = hT @ W_fc.T + b_fc ----
    if (tid < MROWS * VOCAB) {
        int m = tid >> 2, v = tid & 3;
        int row = row0 + m;
        if (row < BB) {
            float        sum = b_fc[v];
            const float* wv  = W_fc + v * HH;
            const float* hr  = hf + m * HH;
#pragma unroll 8
            for (int k = 0; k < HH; ++k) sum = fmaf(hr[k], wv[k], sum);
            out[row * VOCAB + v] = sum;
        }
    }
}

extern "C" void kernel_launch(void* const* d_in, const int* in_sizes, int n_in,
                              void* d_out, int out_size) {
    const void*  x    = d_in[0];
    const float* emb  = (const float*)d_in[1];
    const float* W_ih = (const float*)d_in[2];
    const float* W_hh = (const float*)d_in[3];
    const float* b_ih = (const float*)d_in[4];
    const float* b_hh = (const float*)d_in[5];
    const float* W_fc = (const float*)d_in[6];
    const float* b_fc = (const float*)d_in[7];
    float* out = (float*)d_out;

    static int smem_set = 0;
    if (!smem_set) {
        cudaFuncSetAttribute(gru_kernel,
                             cudaFuncAttributeMaxDynamicSharedMemorySize,
                             SMEM_BYTES);
        smem_set = 1;
    }

    detect_kernel<<<1, 1>>>((const int*)x);
    tok_kernel<<<(BB * TT + 255) / 256, 256>>>(x);
    gi_kernel<<<1, G3>>>(W_ih, emb, b_ih, b_hh);
    gru_kernel<<<NBLK, NTHR, SMEM_BYTES>>>(W_hh, b_hh, W_fc, b_fc, out);
}

// round 17
// speedup vs baseline: 2.6658x; 1.6061x over previous
#include <cuda_runtime.h>
#include <cuda_fp16.h>
#include <cstdint>

#define BB 2048
#define TT 512
#define VOCAB 4
#define EE 64
#define HH 128
#define G3 384
#define NBLK 148
#define MROWS 14
#define BPAD (NBLK * MROWS)
#define NTHR 256
#define GISTR 388      // gi row stride (padded to break bank alignment)

// ---- scratch (no allocs allowed) ----
__device__ float         g_gi[VOCAB * G3];   // b_ih (+ b_hh for r,z) folded in
__device__ unsigned char g_tok[TT * BPAD];   // zero-init => pad rows v=0
__device__ int           g_is64;

// ---- smem layout (bytes) ----
#define OFF_BF   0          // W frags fp16: 48 tiles*8kt*256B = 98304
#define OFF_AH0  98304      // h buf 0: 16*64 u32 = 4096
#define OFF_AH1  102400     // h buf 1
#define OFF_GI   106496     // 4*GISTR f32 = 6208
#define OFF_TOK  112704     // 2*16 int = 128
#define SMEM_BYTES 112832

__device__ __forceinline__ float tanh_fast(float x) {
    float y;
    asm("tanh.approx.f32 %0, %1;" : "=f"(y) : "f"(x));
    return y;
}
__device__ __forceinline__ float sigmoid_fast(float x) {
    return fmaf(tanh_fast(0.5f * x), 0.5f, 0.5f);
}
// pack two f32 -> f16x2 (lo half = a, hi half = b), rn
__device__ __forceinline__ uint32_t pk2(float a, float b) {
    uint32_t r;
    asm("cvt.rn.f16x2.f32 %0, %1, %2;" : "=r"(r) : "f"(b), "f"(a));
    return r;
}
__device__ __forceinline__ void mma_f16(float c[4], const uint32_t a[4],
                                        uint64_t b) {
    uint32_t b0 = (uint32_t)b, b1 = (uint32_t)(b >> 32);
    asm("mma.sync.aligned.m16n8k16.row.col.f32.f16.f16.f32 "
        "{%0,%1,%2,%3}, {%4,%5,%6,%7}, {%8,%9}, {%0,%1,%2,%3};"
        : "+f"(c[0]), "+f"(c[1]), "+f"(c[2]), "+f"(c[3])
        : "r"(a[0]), "r"(a[1]), "r"(a[2]), "r"(a[3]), "r"(b0), "r"(b1));
}

__global__ void detect_kernel(const int* __restrict__ x32) {
    int all_zero = 1;
    for (int i = 1; i < 128; i += 2) all_zero &= (x32[i] == 0);
    g_is64 = all_zero;
}

__global__ void tok_kernel(const void* __restrict__ xraw) {
    int i = blockIdx.x * blockDim.x + threadIdx.x;
    if (i >= BB * TT) return;
    int b = i / TT, t = i % TT;
    int v;
    if (g_is64) v = (int)((const long long*)xraw)[i];
    else        v = ((const int*)xraw)[i];
    g_tok[t * BPAD + b] = (unsigned char)v;
}

// gi[v][g] = b_ih[g] + W_ih[g]·emb[v]  (+ b_hh[g] for gates r,z: g<256)
__global__ void gi_kernel(const float* __restrict__ W_ih,
                          const float* __restrict__ emb,
                          const float* __restrict__ b_ih,
                          const float* __restrict__ b_hh) {
    int g = threadIdx.x;
    if (g >= G3) return;
    float bi = b_ih[g] + (g < 256 ? b_hh[g] : 0.0f);
    for (int v = 0; v < VOCAB; ++v) {
        float s = bi;
#pragma unroll 8
        for (int e = 0; e < EE; ++e) s += W_ih[g * EE + e] * emb[v * EE + e];
        g_gi[v * G3 + g] = s;
    }
}

extern __shared__ char smem[];

__global__ __launch_bounds__(NTHR, 1)
void gru_kernel(const float* __restrict__ W_hh, const float* __restrict__ b_hh,
                const float* __restrict__ W_fc, const float* __restrict__ b_fc,
                float* __restrict__ out) {
    uint64_t* BF     = (uint64_t*)(smem + OFF_BF);
    uint32_t* AHb[2] = {(uint32_t*)(smem + OFF_AH0), (uint32_t*)(smem + OFF_AH1)};
    float*    gi_s   = (float*)(smem + OFF_GI);
    int*      tok_s  = (int*)(smem + OFF_TOK);

    const int tid = threadIdx.x;       // 0..255
    const int l   = tid & 31;
    const int w   = tid >> 5;          // warp 0..7: units [16w, 16w+16)
    const int lg  = l >> 2;            // mma group (row)
    const int lt  = l & 3;             // mma thread-in-group (col pair)
    const int swl = lg << 2;           // A swizzle for rows lg / lg+8
    const int row0 = blockIdx.x * MROWS;

    // ---- stage W fp16 fragments into smem (frag-ordered, one-time) ----
    // entry idx = l + 32*(kt + 8*(tile + 6*warp)),  48 tiles x 8 kt
    for (int idx = tid; idx < 12288; idx += NTHR) {
        int ll = idx & 31, kt = (idx >> 5) & 7, tw = idx >> 8;
        int tile = tw % 6, ww = tw / 6;
        int n = (tile >> 1) * 128 + 16 * ww + 8 * (tile & 1) + (ll >> 2);
        int k = kt * 16 + (ll & 3) * 2;
        const float* Wn = W_hh + n * HH + k;
        uint32_t b0 = pk2(Wn[0], Wn[1]);
        uint32_t b1 = pk2(Wn[8], Wn[9]);
        BF[idx] = (uint64_t)b0 | ((uint64_t)b1 << 32);
    }
    for (int i = tid; i < 1024; i += NTHR) { AHb[0][i] = 0; AHb[1][i] = 0; }
    for (int i = tid; i < VOCAB * G3; i += NTHR)
        gi_s[(i / G3) * GISTR + (i % G3)] = g_gi[i];
    if (tid < 16) {
        tok_s[tid]      = (tid < MROWS) ? (g_tok[row0 + tid] & 3) : 0;
        tok_s[16 + tid] = 0;
    }
    // n-gate bias only (r,z folded into gi table)
    float bN[2][2];
#pragma unroll
    for (int hp = 0; hp < 2; ++hp)
#pragma unroll
        for (int c = 0; c < 2; ++c)
            bN[hp][c] = b_hh[256 + 16 * w + 8 * hp + 2 * lt + c];
    __syncthreads();

    // ---- hoist ALL W fragments into registers (loop-invariant, fp16) ----
    uint64_t Wf[48];                        // [ti*8 + kt]
#pragma unroll
    for (int ti = 0; ti < 6; ++ti)
#pragma unroll
        for (int kt = 0; kt < 8; ++kt)
            Wf[ti * 8 + kt] = BF[(w * 6 + ti) * 256 + kt * 32 + l];

    float hreg[2][2][2];   // [h-half hp][row-half rh][col c], fp32 exact state
#pragma unroll
    for (int hp = 0; hp < 2; ++hp)
#pragma unroll
        for (int rh = 0; rh < 2; ++rh) { hreg[hp][rh][0] = 0.f; hreg[hp][rh][1] = 0.f; }

    for (int t = 0; t < TT; ++t) {
        const int cur = t & 1, nxt = cur ^ 1;
        const uint32_t* Ah = AHb[cur];

        int ntv = 0;
        if (tid < MROWS && t + 1 < TT)
            ntv = g_tok[(t + 1) * BPAD + row0 + tid] & 3;

        // ---- load A fragments (single precision level) ----
        uint32_t Afh[8][4];
#pragma unroll
        for (int kc = 0; kc < 8; ++kc) {
            int w0 = kc * 8 + lt;
            int p0 = lg * 64 + (w0 ^ swl);
            int p2 = lg * 64 + ((w0 + 4) ^ swl);
            Afh[kc][0] = Ah[p0];       Afh[kc][1] = Ah[p0 + 512];
            Afh[kc][2] = Ah[p2];       Afh[kc][3] = Ah[p2 + 512];
        }

        float C[6][4];
#pragma unroll
        for (int ti = 0; ti < 4; ++ti) {       // r,z gates: bias in gi table
            C[ti][0] = 0.f; C[ti][1] = 0.f; C[ti][2] = 0.f; C[ti][3] = 0.f;
        }
#pragma unroll
        for (int hp = 0; hp < 2; ++hp) {       // n gate: bias inside r*( )
            C[4 + hp][0] = bN[hp][0]; C[4 + hp][1] = bN[hp][1];
            C[4 + hp][2] = bN[hp][0]; C[4 + hp][3] = bN[hp][1];
        }

        // ---- single pass: A x W (all registers) ----
#pragma unroll
        for (int kt = 0; kt < 8; ++kt)
#pragma unroll
            for (int ti = 0; ti < 6; ++ti)
                mma_f16(C[ti], Afh[kt], Wf[ti * 8 + kt]);

        // ---- gates + h update (thread-local via C-frag ownership) ----
        uint32_t* AhN = AHb[nxt];
#pragma unroll
        for (int hp = 0; hp < 2; ++hp) {
#pragma unroll
            for (int rh = 0; rh < 2; ++rh) {
                int m = lg + 8 * rh;
                int v = tok_s[cur * 16 + m];
                const float* gv = gi_s + v * GISTR + 16 * w + 8 * hp + 2 * lt;
                float hn01[2];
#pragma unroll
                for (int c = 0; c < 2; ++c) {
                    int  reg = 2 * rh + c;
                    float r = sigmoid_fast(gv[c]       + C[hp][reg]);
                    float z = sigmoid_fast(gv[128 + c] + C[2 + hp][reg]);
                    float n = tanh_fast   (gv[256 + c] + r * C[4 + hp][reg]);
                    float hn = fmaf(z, hreg[hp][rh][c] - n, n);
                    hreg[hp][rh][c] = hn;
                    hn01[c] = hn;
                }
                int word = (8 * w + 4 * hp + lt) ^ swl;   // swizzle f(m&7)=lg
                AhN[m * 64 + word] = pk2(hn01[0], hn01[1]);
            }
        }
        if (tid < MROWS) tok_s[nxt * 16 + tid] = ntv;
        __syncthreads();
    }

    // ---- final h (fp32, from regs) -> smem (reuse BF region) ----
    float* hf = (float*)(smem + OFF_BF);
#pragma unroll
    for (int hp = 0; hp < 2; ++hp)
#pragma unroll
        for (int rh = 0; rh < 2; ++rh)
#pragma unroll
            for (int c = 0; c < 2; ++c) {
                int m = lg + 8 * rh;
                int u = 16 * w + 8 * hp + 2 * lt + c;
                hf[m * HH + u] = hreg[hp][rh][c];
            }
    __syncthreads();

    // ---- logits = hT @ W_fc.T + b_fc ----
    if (tid < MROWS * VOCAB) {
        int m = tid >> 2, v = tid & 3;
        int row = row0 + m;
        if (row < BB) {
            float        sum = b_fc[v];
            const float* wv  = W_fc + v * HH;
            const float* hr  = hf + m * HH;
#pragma unroll 8
            for (int k = 0; k < HH; ++k) sum = fmaf(hr[k], wv[k], sum);
            out[row * VOCAB + v] = sum;
        }
    }
}

extern "C" void kernel_launch(void* const* d_in, const int* in_sizes, int n_in,
                              void* d_out, int out_size) {
    const void*  x    = d_in[0];
    const float* emb  = (const float*)d_in[1];
    const float* W_ih = (const float*)d_in[2];
    const float* W_hh = (const float*)d_in[3];
    const float* b_ih = (const float*)d_in[4];
    const float* b_hh = (const float*)d_in[5];
    const float* W_fc = (const float*)d_in[6];
    const float* b_fc = (const float*)d_in[7];
    float* out = (float*)d_out;

    static int smem_set = 0;
    if (!smem_set) {
        cudaFuncSetAttribute(gru_kernel,
                             cudaFuncAttributeMaxDynamicSharedMemorySize,
                             SMEM_BYTES);
        smem_set = 1;
    }

    detect_kernel<<<1, 1>>>((const int*)x);
    tok_kernel<<<(BB * TT + 255) / 256, 256>>>(x);
    gi_kernel<<<1, G3>>>(W_ih, emb, b_ih, b_hh);
    gru_kernel<<<NBLK, NTHR, SMEM_BYTES>>>(W_hh, b_hh, W_fc, b_fc, out);
}